// round 15
// baseline (speedup 1.0000x reference)
#include <cuda_runtime.h>
#include <cstdint>

using ull = unsigned long long;

constexpr int S  = 1024;
constexpr int HD = 256;
constexpr int NB = 128;

// Precomputed input projections: XG[b][s][gate*256 + j], gate order z,r,c
__device__ float XG_buf[(size_t)NB * S * 768];

__device__ __forceinline__ void ffma2(ull& d, ull a, ull b) {
    asm("fma.rn.f32x2 %0, %1, %2, %0;" : "+l"(d) : "l"(a), "l"(b));
}
__device__ __forceinline__ float2 unpk(ull a) {
    float2 r; asm("mov.b64 {%0, %1}, %2;" : "=f"(r.x), "=f"(r.y) : "l"(a)); return r;
}
__device__ __forceinline__ uint32_t smem_u32(const void* p) {
    uint32_t a;
    asm("{ .reg .u64 t; cvta.to.shared.u64 t, %1; cvt.u32.u64 %0, t; }" : "=r"(a) : "l"(p));
    return a;
}
__device__ __forceinline__ uint32_t mapa_rank(uint32_t addr, uint32_t rank) {
    uint32_t r; asm("mapa.shared::cluster.u32 %0, %1, %2;" : "=r"(r) : "r"(addr), "r"(rank));
    return r;
}
__device__ __forceinline__ void st_clu_v4(uint32_t addr, float4 v) {
    asm volatile("st.shared::cluster.v4.f32 [%0], {%1,%2,%3,%4};"
                 :: "r"(addr), "f"(v.x), "f"(v.y), "f"(v.z), "f"(v.w) : "memory");
}
__device__ __forceinline__ void clu_arrive() {
    asm volatile("barrier.cluster.arrive.aligned;" ::: "memory");
}
__device__ __forceinline__ void clu_wait() {
    asm volatile("barrier.cluster.wait.aligned;" ::: "memory");
}
__device__ __forceinline__ void mbar_init(uint32_t addr, uint32_t cnt) {
    asm volatile("mbarrier.init.shared.b64 [%0], %1;" :: "r"(addr), "r"(cnt) : "memory");
}
__device__ __forceinline__ void mbar_arrive_remote(uint32_t addr) {
    asm volatile("mbarrier.arrive.release.cluster.shared::cluster.b64 _, [%0];"
                 :: "r"(addr) : "memory");
}
__device__ __forceinline__ void mbar_wait(uint32_t addr, uint32_t parity) {
    asm volatile(
        "{\n\t.reg .pred P;\n\t"
        "LW%=:\n\t"
        "mbarrier.try_wait.parity.acquire.cluster.shared::cta.b64 P, [%0], %1, 0x989680;\n\t"
        "@P bra LD%=;\n\t"
        "bra LW%=;\n\t"
        "LD%=:\n\t}"
        :: "r"(addr), "r"(parity) : "memory");
}
__device__ __forceinline__ float sigm(float x) { return 1.0f / (1.0f + __expf(-x)); }
__device__ __forceinline__ float tanh_f(float x) {
    x = fminf(fmaxf(x, -15.0f), 15.0f);
    float e = __expf(-2.0f * x);
    return __fdividef(1.0f - e, 1.0f + e);
}
// quad rotation swizzle: logical quad q -> physical quad (rotate within 8-quad group)
__device__ __forceinline__ int swq(int q) { return (q & ~7) | ((q + (q >> 3)) & 7); }

// ============================================================================
// Phase 1: XG = x @ Wg^T + bias  (proven fp32 FFMA2 version, ~1.37 ms)
// ============================================================================
constexpr int PRE_SMEM_FLOATS = 32768 + 64 * 260;
constexpr size_t PRE_SMEM_BYTES = PRE_SMEM_FLOATS * sizeof(float);

__global__ void __launch_bounds__(256, 1)
xproj_kernel(const float* __restrict__ x,
             const float* __restrict__ Wzx, const float* __restrict__ bz,
             const float* __restrict__ Wrx, const float* __restrict__ br,
             const float* __restrict__ Wcx, const float* __restrict__ bc)
{
    extern __shared__ float smp[];
    float* XS = smp;            // [128][256]
    float* WS = smp + 32768;    // [64][260]

    const int tid = threadIdx.x, w = tid >> 5, lane = tid & 31;
    const int nt = blockIdx.x % 12, mg = blockIdx.x / 12;
    const int gate = nt >> 2, j0 = (nt & 3) * 64;

    const float* Wsrc = (gate == 0 ? Wzx : (gate == 1 ? Wrx : Wcx)) + (size_t)j0 * HD;
    const float* bsrc = (gate == 0 ? bz : (gate == 1 ? br : bc)) + j0;
    const float b0v = bsrc[lane];
    const float b1v = bsrc[lane + 32];

    for (int i = tid; i < 64 * 64; i += 256) {
        int row = i >> 6, q = i & 63;
        *(float4*)(WS + row * 260 + q * 4) = *(const float4*)(Wsrc + row * 256 + q * 4);
    }

    const int r0 = w * 16;
    for (int it = 0; it < 8; ++it) {
        const int m = mg * 8 + it;
        __syncthreads();
        const float* xs = x + (size_t)m * 128 * HD;
#pragma unroll 8
        for (int i = tid; i < 8192; i += 256)
            *(float4*)(XS + i * 4) = *(const float4*)(xs + (size_t)i * 4);
        __syncthreads();

        ull acc[32];
#pragma unroll
        for (int i = 0; i < 32; ++i) acc[i] = 0ull;

#pragma unroll 4
        for (int kq = 0; kq < 64; ++kq) {
            ulonglong2 wv0 = *(const ulonglong2*)(WS + lane * 260 + kq * 4);
            ulonglong2 wv1 = *(const ulonglong2*)(WS + (lane + 32) * 260 + kq * 4);
#pragma unroll
            for (int r = 0; r < 16; ++r) {
                ulonglong2 xv = *(const ulonglong2*)(XS + (r0 + r) * 256 + kq * 4);
                ffma2(acc[r * 2 + 0], xv.x, wv0.x);
                ffma2(acc[r * 2 + 0], xv.y, wv0.y);
                ffma2(acc[r * 2 + 1], xv.x, wv1.x);
                ffma2(acc[r * 2 + 1], xv.y, wv1.y);
            }
        }

        float* op = XG_buf + ((size_t)m * 128 + r0) * 768 + gate * 256 + j0;
#pragma unroll
        for (int r = 0; r < 16; ++r) {
            float2 f0 = unpk(acc[r * 2 + 0]);
            float2 f1 = unpk(acc[r * 2 + 1]);
            op[(size_t)r * 768 + lane]      = f0.x + f0.y + b0v;
            op[(size_t)r * 768 + lane + 32] = f1.x + f1.y + b1v;
        }
    }
}

// ============================================================================
// Phase 2: recurrence. 32 clusters x 4 CTAs x 512 threads.
// Two interleaved groups (A = rows 0-1, B = rows 2-3) with 4 mbarriers so
// each sync's latency hides under the other group's compute.
// Phase1 (z+r): W in regs (2j x 32k / thread). Phase2 (c): Wc in SMEM.
// ============================================================================
constexpr int R_WC = 0;                 // [64][256] c-gate weights, quad-swizzled
constexpr int R_G0 = 16384;             // group A block
constexpr int R_G1 = 18432;             // group B block (stride 2048)
constexpr int GH  = 0;                  // [2][260] h, quad-swizzled
constexpr int GRH = 528;                // [2][260] r*h
constexpr int GZ  = 1056;               // [2][68]  z
constexpr int GX  = 1200;               // [2buf][2][204] xg  (816)
constexpr int R_MB_BYTE = 81920;        // 4 mbarriers (32 B) at float 20480
constexpr int REC_FLOATS = 20488;
constexpr size_t REC_SMEM_BYTES = REC_FLOATS * sizeof(float);  // 81952 B

__global__ void __cluster_dims__(4, 1, 1) __launch_bounds__(512, 1)
gru_rec(const float* __restrict__ h0,
        const float* __restrict__ Wzh, const float* __restrict__ Wrh,
        const float* __restrict__ Wch, float* __restrict__ out)
{
    extern __shared__ float sm[];

    const int tid  = threadIdx.x;
    const int wid  = tid >> 5;
    const int lane = tid & 31;
    const int rank = blockIdx.x & 3;
    const int b0   = (blockIdx.x >> 2) << 2;
    const int j0   = rank << 6;

    // phase-1 identity
    const int g1 = wid >> 3;           // z: warps 0-7, r: warps 8-15
    const int jb = (wid & 7) * 8;
    const int jl = lane >> 3;          // 2 j each
    const int kl = lane & 7;           // 32 k each
    // phase-2 identity
    const int b2p = lane >> 4;         // 0/1 batch row within group
    const int ksp = lane & 15;         // 16 k each
    const int jc  = wid * 4;

    // ---- init SMEM ----
    for (int i = tid; i < 4096; i += 512) {
        int row = i >> 6, q = i & 63;
        *(float4*)(sm + R_WC + row * 256 + swq(q) * 4) =
            *(const float4*)(Wch + (size_t)(j0 + row) * 256 + q * 4);
    }
    for (int i = tid; i < 256; i += 512) {
        int bb = i >> 6, q = i & 63;          // bb 0..3 -> group bb>>1, row bb&1
        int gb = (bb >> 1) ? R_G1 : R_G0;
        *(float4*)(sm + gb + GH + (bb & 1) * 260 + swq(q) * 4) =
            *(const float4*)(h0 + (size_t)(b0 + bb) * 256 + q * 4);
    }
    // preload XG t=0 into buffer 0 (192 float4: 2 groups x 2 rows x 3 gates x 16)
    if (tid < 192) {
        int g = tid / 96, r2 = tid % 96, pb = r2 / 48, rem = r2 % 48;
        int pg = rem >> 4, pq = rem & 15;
        float4 v = *(const float4*)(XG_buf + ((size_t)(b0 + g * 2 + pb) * S) * 768
                                    + pg * 256 + j0 + pq * 4);
        int gb = g ? R_G1 : R_G0;
        *(float4*)(sm + gb + GX + pb * 204 + pg * 68 + pq * 4) = v;
    }

    // ---- phase-1 weights -> registers (2 j x 32 k per thread) ----
    ull w1[32];
    {
        const float* wsrc = (g1 == 0 ? Wzh : Wrh)
                          + (size_t)(j0 + jb + jl * 2) * 256 + kl * 32;
#pragma unroll
        for (int jt = 0; jt < 2; ++jt)
#pragma unroll
            for (int c = 0; c < 4; ++c) {
                ulonglong2 v0 = *(const ulonglong2*)(wsrc + jt * 256 + c * 8);
                ulonglong2 v1 = *(const ulonglong2*)(wsrc + jt * 256 + c * 8 + 4);
                w1[jt * 16 + c * 4 + 0] = v0.x;
                w1[jt * 16 + c * 4 + 1] = v0.y;
                w1[jt * 16 + c * 4 + 2] = v1.x;
                w1[jt * 16 + c * 4 + 3] = v1.y;
            }
    }

    const uint32_t base = smem_u32(sm);
    const uint32_t mymb = base + (uint32_t)R_MB_BYTE;
    if (tid == 0) {
        mbar_init(mymb + 0, 64);    // A1
        mbar_init(mymb + 8, 64);    // B1
        mbar_init(mymb + 16, 64);   // A2
        mbar_init(mymb + 24, 64);   // B2
    }
    __syncthreads();
    clu_arrive(); clu_wait();

    uint32_t rbase[4];
#pragma unroll
    for (int p = 0; p < 4; ++p) rbase[p] = mapa_rank(base, p);

    const int qr = rank * 16 + ((jb + jl * 2) >> 2);
    const uint32_t offRH_q = (uint32_t)(GRH + swq(qr) * 4) * 4u;   // within group (bytes)
    const int qh = rank * 16 + wid;
    const uint32_t offH_q = (uint32_t)(GH + swq(qh) * 4) * 4u;

    const float* wp2 = sm + R_WC + jc * 256;
    float* outpA = out + (size_t)(b0 + b2p) * S * 256 + (j0 + jc);
    float* outpB = outpA + (size_t)2 * S * 256;

    // XG prefetch identity (tid < 192)
    const int pgG = tid / 96, pr2 = tid % 96, ppb = pr2 / 48, prem = pr2 % 48;
    const int ppg = prem >> 4, ppq = prem & 15;
    const float* psrc = XG_buf + (size_t)(b0 + pgG * 2 + ppb) * S * 768
                        + ppg * 256 + j0 + ppq * 4;
    const int pdst = (pgG ? R_G1 : R_G0) + GX + ppb * 204 + ppg * 68 + ppq * 4;

    for (int t = 0; t < S; ++t) {
        const uint32_t par = (uint32_t)(t & 1);

        // prefetch next step's XG (global -> regs)
        float4 pxv;
        if (tid < 192 && t + 1 < S)
            pxv = *(const float4*)(psrc + (size_t)(t + 1) * 768);

        // ---------------- per-group phase 1 (z / r) ----------------
        auto p1 = [&](int gb, const float* xgb) {
            ull acc[4] = {0ull, 0ull, 0ull, 0ull};
#pragma unroll
            for (int c = 0; c < 4; ++c) {
#pragma unroll
                for (int b = 0; b < 2; ++b) {
                    const float* hb = sm + gb + GH + b * 260;
                    const int p0 = (kl << 3) | ((2 * c + kl) & 7);
                    const int p1_ = (kl << 3) | ((2 * c + 1 + kl) & 7);
                    ulonglong2 h0v = *(const ulonglong2*)(hb + p0 * 4);
                    ulonglong2 h1v = *(const ulonglong2*)(hb + p1_ * 4);
#pragma unroll
                    for (int jt = 0; jt < 2; ++jt) {
                        ffma2(acc[b * 2 + jt], h0v.x, w1[jt * 16 + c * 4 + 0]);
                        ffma2(acc[b * 2 + jt], h0v.y, w1[jt * 16 + c * 4 + 1]);
                        ffma2(acc[b * 2 + jt], h1v.x, w1[jt * 16 + c * 4 + 2]);
                        ffma2(acc[b * 2 + jt], h1v.y, w1[jt * 16 + c * 4 + 3]);
                    }
                }
            }
            float s[4];
#pragma unroll
            for (int o = 0; o < 4; ++o) {
                float2 f = unpk(acc[o]);
                float v = f.x + f.y;
                v += __shfl_xor_sync(0xffffffffu, v, 1);
                v += __shfl_xor_sync(0xffffffffu, v, 2);
                v += __shfl_xor_sync(0xffffffffu, v, 4);
                s[o] = v;
            }
            if (kl == 0) {
                if (g1 == 0) {
#pragma unroll
                    for (int b = 0; b < 2; ++b) {
                        int jloc = jb + jl * 2;
                        float z0 = sigm(s[b * 2 + 0] + xgb[b * 204 + jloc]);
                        float z1 = sigm(s[b * 2 + 1] + xgb[b * 204 + jloc + 1]);
                        *(float2*)(sm + gb + GZ + b * 68 + jloc) = make_float2(z0, z1);
                    }
                } else {
                    float rr[4];
#pragma unroll
                    for (int b = 0; b < 2; ++b)
#pragma unroll
                        for (int jt = 0; jt < 2; ++jt) {
                            int jloc = jb + jl * 2 + jt;
                            int e = j0 + jloc;
                            float hp = sm[gb + GH + b * 260 + swq(e >> 2) * 4 + (e & 3)];
                            rr[b * 2 + jt] =
                                sigm(s[b * 2 + jt] + xgb[b * 204 + 68 + jloc]) * hp;
                        }
                    float pr[4];
#pragma unroll
                    for (int o = 0; o < 4; ++o)
                        pr[o] = __shfl_xor_sync(0x01010101u, rr[o], 8);
                    if ((jl & 1) == 0) {
#pragma unroll
                        for (int b = 0; b < 2; ++b) {
                            float4 v = make_float4(rr[b * 2], rr[b * 2 + 1],
                                                   pr[b * 2], pr[b * 2 + 1]);
                            uint32_t off = (uint32_t)gb * 4u + offRH_q + (uint32_t)b * 1040u;
#pragma unroll
                            for (int p = 0; p < 4; ++p) st_clu_v4(rbase[p] + off, v);
                        }
                    }
                }
            }
        };

        // ---------------- per-group phase 2 (candidate) ----------------
        auto p2 = [&](int gb, const float* xgb, float* outg) {
            const float* Rb = sm + gb + GRH + b2p * 260;
            ull cacc[4] = {0ull, 0ull, 0ull, 0ull};
#pragma unroll
            for (int i = 0; i < 4; ++i) {
                const int pq2 = ksp * 4 + ((i + ksp) & 3);
                ulonglong2 rv = *(const ulonglong2*)(Rb + pq2 * 4);
#pragma unroll
                for (int jj = 0; jj < 4; ++jj) {
                    ulonglong2 wv = *(const ulonglong2*)(wp2 + jj * 256 + pq2 * 4);
                    ffma2(cacc[jj], rv.x, wv.x);
                    ffma2(cacc[jj], rv.y, wv.y);
                }
            }
            float cv[4];
#pragma unroll
            for (int o = 0; o < 4; ++o) {
                float2 f = unpk(cacc[o]);
                float v = f.x + f.y;
                v += __shfl_xor_sync(0xffffffffu, v, 1);
                v += __shfl_xor_sync(0xffffffffu, v, 2);
                v += __shfl_xor_sync(0xffffffffu, v, 4);
                v += __shfl_xor_sync(0xffffffffu, v, 8);
                cv[o] = v;
            }
            if (ksp == 0) {
                float4 hp = *(const float4*)(sm + gb + GH + b2p * 260 + swq(qh) * 4);
                float4 zg = *(const float4*)(sm + gb + GZ + b2p * 68 + jc);
                const float* xc = xgb + b2p * 204 + 136 + jc;
                float4 hn;
                hn.x = fmaf(zg.x, tanh_f(cv[0] + xc[0]) - hp.x, hp.x);
                hn.y = fmaf(zg.y, tanh_f(cv[1] + xc[1]) - hp.y, hp.y);
                hn.z = fmaf(zg.z, tanh_f(cv[2] + xc[2]) - hp.z, hp.z);
                hn.w = fmaf(zg.w, tanh_f(cv[3] + xc[3]) - hp.w, hp.w);
                uint32_t off = (uint32_t)gb * 4u + offH_q + (uint32_t)b2p * 1040u;
#pragma unroll
                for (int p = 0; p < 4; ++p) st_clu_v4(rbase[p] + off, hn);
                *(float4*)(outg + (size_t)t * 256) = hn;
            }
        };

        const float* xgA = sm + R_G0 + GX + (t & 1) * 408;
        const float* xgB = sm + R_G1 + GX + (t & 1) * 408;

        if (t) mbar_wait(mymb + 16, par ^ 1);       // A2 of t-1
        p1(R_G0, xgA);
        __syncwarp();
        if (lane == 0) {
#pragma unroll
            for (int p = 0; p < 4; ++p)
                mbar_arrive_remote(rbase[p] + (uint32_t)R_MB_BYTE + 0);   // A1
        }

        // commit next-step XG (before B arrives so t+1 readers see it)
        if (tid < 192 && t + 1 < S)
            *(float4*)(sm + pdst + ((t + 1) & 1) * 408) = pxv;

        if (t) mbar_wait(mymb + 24, par ^ 1);       // B2 of t-1
        p1(R_G1, xgB);
        __syncwarp();
        if (lane == 0) {
#pragma unroll
            for (int p = 0; p < 4; ++p)
                mbar_arrive_remote(rbase[p] + (uint32_t)R_MB_BYTE + 8);   // B1
        }

        mbar_wait(mymb + 0, par);                   // A1
        p2(R_G0, xgA, outpA);
        __syncwarp();
        if (lane == 0) {
#pragma unroll
            for (int p = 0; p < 4; ++p)
                mbar_arrive_remote(rbase[p] + (uint32_t)R_MB_BYTE + 16);  // A2
        }

        mbar_wait(mymb + 8, par);                   // B1
        p2(R_G1, xgB, outpB);
        __syncwarp();
        if (lane == 0) {
#pragma unroll
            for (int p = 0; p < 4; ++p)
                mbar_arrive_remote(rbase[p] + (uint32_t)R_MB_BYTE + 24);  // B2
        }
    }
    clu_arrive(); clu_wait();   // don't exit while peers' pushes are in flight
}

extern "C" void kernel_launch(void* const* d_in, const int* in_sizes, int n_in,
                              void* d_out, int out_size) {
    const float* x   = (const float*)d_in[0];
    const float* h0  = (const float*)d_in[1];
    const float* Wzx = (const float*)d_in[2];
    const float* bz  = (const float*)d_in[3];
    const float* Wzh = (const float*)d_in[4];
    const float* Wrx = (const float*)d_in[5];
    const float* br  = (const float*)d_in[6];
    const float* Wrh = (const float*)d_in[7];
    const float* Wcx = (const float*)d_in[8];
    const float* bc  = (const float*)d_in[9];
    const float* Wch = (const float*)d_in[10];
    float* out = (float*)d_out;

    cudaFuncSetAttribute(xproj_kernel, cudaFuncAttributeMaxDynamicSharedMemorySize,
                         (int)PRE_SMEM_BYTES);
    cudaFuncSetAttribute(gru_rec, cudaFuncAttributeMaxDynamicSharedMemorySize,
                         (int)REC_SMEM_BYTES);

    xproj_kernel<<<12 * 128, 256, PRE_SMEM_BYTES>>>(x, Wzx, bz, Wrx, br, Wcx, bc);
    gru_rec<<<128, 512, REC_SMEM_BYTES>>>(h0, Wzh, Wrh, Wch, out);
}

// round 17
// speedup vs baseline: 3.0403x; 3.0403x over previous
#include <cuda_runtime.h>
#include <cstdint>

using ull = unsigned long long;

constexpr int S  = 1024;
constexpr int HD = 256;
constexpr int NB = 128;

// Precomputed input projections: XG[b][s][gate*256 + j], gate order z,r,c
__device__ float XG_buf[(size_t)NB * S * 768];

__device__ __forceinline__ void ffma2(ull& d, ull a, ull b) {
    asm("fma.rn.f32x2 %0, %1, %2, %0;" : "+l"(d) : "l"(a), "l"(b));
}
__device__ __forceinline__ float2 unpk(ull a) {
    float2 r; asm("mov.b64 {%0, %1}, %2;" : "=f"(r.x), "=f"(r.y) : "l"(a)); return r;
}
__device__ __forceinline__ uint32_t smem_u32(const void* p) {
    uint32_t a;
    asm("{ .reg .u64 t; cvta.to.shared.u64 t, %1; cvt.u32.u64 %0, t; }" : "=r"(a) : "l"(p));
    return a;
}
__device__ __forceinline__ uint32_t mapa_rank(uint32_t addr, uint32_t rank) {
    uint32_t r; asm("mapa.shared::cluster.u32 %0, %1, %2;" : "=r"(r) : "r"(addr), "r"(rank));
    return r;
}
__device__ __forceinline__ void st_clu_v4(uint32_t addr, float4 v) {
    asm volatile("st.shared::cluster.v4.f32 [%0], {%1,%2,%3,%4};"
                 :: "r"(addr), "f"(v.x), "f"(v.y), "f"(v.z), "f"(v.w) : "memory");
}
__device__ __forceinline__ void clu_arrive() {
    asm volatile("barrier.cluster.arrive.aligned;" ::: "memory");
}
__device__ __forceinline__ void clu_wait() {
    asm volatile("barrier.cluster.wait.aligned;" ::: "memory");
}
__device__ __forceinline__ float sigm(float x) { return 1.0f / (1.0f + __expf(-x)); }
__device__ __forceinline__ float tanh_f(float x) {
    x = fminf(fmaxf(x, -15.0f), 15.0f);
    float e = __expf(-2.0f * x);
    return __fdividef(1.0f - e, 1.0f + e);
}
// quad rotation swizzle: logical quad q -> physical quad (rotate within 8-quad group)
__device__ __forceinline__ int swq(int q) { return (q & ~7) | ((q + (q >> 3)) & 7); }

// ============================================================================
// Phase 1: XG = x @ Wg^T + bias — m-tile-resident loop order (x read ONCE).
// grid = 1024 m-tiles; each CTA: X tile in SMEM, loop 12 (gate, j0) n-tiles,
// reloading the 64KB W tile per n-tile (L2-resident after first wave).
// ============================================================================
constexpr int PRE_SMEM_FLOATS = 32768 + 64 * 260;   // X [128][256] + W [64][260]
constexpr size_t PRE_SMEM_BYTES = PRE_SMEM_FLOATS * sizeof(float);  // 197632 B

__global__ void __launch_bounds__(256, 1)
xproj_kernel(const float* __restrict__ x,
             const float* __restrict__ Wzx, const float* __restrict__ bz,
             const float* __restrict__ Wrx, const float* __restrict__ br,
             const float* __restrict__ Wcx, const float* __restrict__ bc)
{
    extern __shared__ float smp[];
    float* XS = smp;            // [128][256]
    float* WS = smp + 32768;    // [64][260]

    const int tid = threadIdx.x, w = tid >> 5, lane = tid & 31;
    const int m = blockIdx.x;               // m-tile: rows [m*128, m*128+128)
    const int r0 = w * 16;

    // load X tile once (DRAM, 128 KB)
    const float* xs = x + (size_t)m * 128 * HD;
#pragma unroll 8
    for (int i = tid; i < 8192; i += 256)
        *(float4*)(XS + i * 4) = *(const float4*)(xs + (size_t)i * 4);

    const float* wsrcs[3] = {Wzx, Wrx, Wcx};
    const float* bsrcs[3] = {bz, br, bc};

    for (int nt = 0; nt < 12; ++nt) {
        const int gate = nt >> 2, j0 = (nt & 3) * 64;
        const float* Wsrc = wsrcs[gate] + (size_t)j0 * HD;
        const float* bsrc = bsrcs[gate] + j0;
        const float b0v = bsrc[lane];
        const float b1v = bsrc[lane + 32];

        __syncthreads();   // previous n-tile done reading WS (and X tile ready)
        for (int i = tid; i < 64 * 64; i += 256) {
            int row = i >> 6, q = i & 63;
            *(float4*)(WS + row * 260 + q * 4) =
                *(const float4*)(Wsrc + row * 256 + q * 4);
        }
        __syncthreads();

        ull acc[32];
#pragma unroll
        for (int i = 0; i < 32; ++i) acc[i] = 0ull;

#pragma unroll 4
        for (int kq = 0; kq < 64; ++kq) {
            ulonglong2 wv0 = *(const ulonglong2*)(WS + lane * 260 + kq * 4);
            ulonglong2 wv1 = *(const ulonglong2*)(WS + (lane + 32) * 260 + kq * 4);
#pragma unroll
            for (int r = 0; r < 16; ++r) {
                ulonglong2 xv = *(const ulonglong2*)(XS + (r0 + r) * 256 + kq * 4);
                ffma2(acc[r * 2 + 0], xv.x, wv0.x);
                ffma2(acc[r * 2 + 0], xv.y, wv0.y);
                ffma2(acc[r * 2 + 1], xv.x, wv1.x);
                ffma2(acc[r * 2 + 1], xv.y, wv1.y);
            }
        }

        float* op = XG_buf + ((size_t)m * 128 + r0) * 768 + gate * 256 + j0;
#pragma unroll
        for (int r = 0; r < 16; ++r) {
            float2 f0 = unpk(acc[r * 2 + 0]);
            float2 f1 = unpk(acc[r * 2 + 1]);
            op[(size_t)r * 768 + lane]      = f0.x + f0.y + b0v;
            op[(size_t)r * 768 + lane + 32] = f1.x + f1.y + b1v;
        }
    }
}

// ============================================================================
// Phase 2: recurrence (R7/R8 structure — twice-verified best, 4.71 ms).
// 32 clusters x 4 CTAs, 512 threads.
// Phase1 (z+r): weights in REGISTERS. Phase2 (c): weights in SMEM.
// barrier.cluster x2 per step.
// ============================================================================
constexpr int R_WC = 0;                    // [64][256] c-gate weights, quad-swizzled
constexpr int R_H  = 16384;                // [4][260]  h, quad-swizzled rows
constexpr int R_RH = 17424;                // [4][260]  r*h, quad-swizzled rows
constexpr int R_Z  = 18464;                // [4][68]
constexpr int R_XG = 18736;                // [2][4][3][68] = 1632 floats
constexpr int REC_FLOATS = R_XG + 1632;    // 20368
constexpr size_t REC_SMEM_BYTES = REC_FLOATS * sizeof(float);  // ~81.5 KB

__global__ void __cluster_dims__(4, 1, 1) __launch_bounds__(512, 1)
gru_rec(const float* __restrict__ h0,
        const float* __restrict__ Wzh, const float* __restrict__ Wrh,
        const float* __restrict__ Wch, float* __restrict__ out)
{
    extern __shared__ float sm[];

    const int tid  = threadIdx.x;
    const int wid  = tid >> 5;
    const int lane = tid & 31;
    const int rank = blockIdx.x & 3;
    const int b0   = (blockIdx.x >> 2) << 2;
    const int j0   = rank << 6;

    const int g1 = wid >> 3;
    const int jb = (wid & 7) * 8;
    const int jl = lane >> 3;
    const int kl = lane & 7;
    const int b2 = lane & 3;
    const int ks = lane >> 2;
    const int jc = wid * 4;

    for (int i = tid; i < 4096; i += 512) {
        int row = i >> 6, q = i & 63;
        *(float4*)(sm + R_WC + row * 256 + swq(q) * 4) =
            *(const float4*)(Wch + (size_t)(j0 + row) * 256 + q * 4);
    }
    for (int i = tid; i < 256; i += 512) {
        int bb = i >> 6, q = i & 63;
        *(float4*)(sm + R_H + bb * 260 + swq(q) * 4) =
            *(const float4*)(h0 + (size_t)(b0 + bb) * 256 + q * 4);
    }
    if (tid < 192) {
        int pb = tid / 48, rem = tid % 48, pg = rem >> 4, pq = rem & 15;
        float4 v = *(const float4*)(XG_buf + ((size_t)(b0 + pb) * S + 0) * 768
                                    + pg * 256 + j0 + pq * 4);
        *(float4*)(sm + R_XG + pb * 204 + pg * 68 + pq * 4) = v;
    }

    ull w1[32];
    {
        const float* wsrc = (g1 == 0 ? Wzh : Wrh)
                          + (size_t)(j0 + jb + jl * 2) * 256 + kl * 32;
#pragma unroll
        for (int jt = 0; jt < 2; ++jt)
#pragma unroll
            for (int c = 0; c < 4; ++c) {
                ulonglong2 v0 = *(const ulonglong2*)(wsrc + jt * 256 + c * 8);
                ulonglong2 v1 = *(const ulonglong2*)(wsrc + jt * 256 + c * 8 + 4);
                w1[jt * 16 + c * 4 + 0] = v0.x;
                w1[jt * 16 + c * 4 + 1] = v0.y;
                w1[jt * 16 + c * 4 + 2] = v1.x;
                w1[jt * 16 + c * 4 + 3] = v1.y;
            }
    }
    __syncthreads();
    clu_arrive(); clu_wait();

    const uint32_t base = smem_u32(sm);
    uint32_t rbase[4];
#pragma unroll
    for (int p = 0; p < 4; ++p) rbase[p] = mapa_rank(base, p);

    const int qr = rank * 16 + ((jb + jl * 2) >> 2);
    const uint32_t offRH = (uint32_t)(R_RH + swq(qr) * 4) * 4u;
    const int qh = rank * 16 + wid;
    const uint32_t offH = (uint32_t)(R_H + swq(qh) * 4) * 4u;

    const float* wp2 = sm + R_WC + jc * 256;
    float* outp = out + (size_t)(b0 + b2) * S * 256 + (j0 + jc);

    const int pb = tid / 48, prem = tid % 48, pg = prem >> 4, pq = prem & 15;
    const float* psrc = XG_buf + (size_t)(b0 + pb) * S * 768 + pg * 256 + j0 + pq * 4;

    for (int t = 0; t < S; ++t) {
        float4 pxv;
        if (tid < 192 && t + 1 < S)
            pxv = *(const float4*)(psrc + (size_t)(t + 1) * 768);

        const float* xgb = sm + R_XG + (t & 1) * 816;

        ull acc[8];
#pragma unroll
        for (int i = 0; i < 8; ++i) acc[i] = 0ull;
#pragma unroll
        for (int c = 0; c < 4; ++c) {
#pragma unroll
            for (int b = 0; b < 4; ++b) {
                const float* hb = sm + R_H + b * 260;
                const int p0 = (kl << 3) | ((2 * c + kl) & 7);
                const int p1 = (kl << 3) | ((2 * c + 1 + kl) & 7);
                ulonglong2 h0v = *(const ulonglong2*)(hb + p0 * 4);
                ulonglong2 h1v = *(const ulonglong2*)(hb + p1 * 4);
#pragma unroll
                for (int jt = 0; jt < 2; ++jt) {
                    ffma2(acc[b * 2 + jt], h0v.x, w1[jt * 16 + c * 4 + 0]);
                    ffma2(acc[b * 2 + jt], h0v.y, w1[jt * 16 + c * 4 + 1]);
                    ffma2(acc[b * 2 + jt], h1v.x, w1[jt * 16 + c * 4 + 2]);
                    ffma2(acc[b * 2 + jt], h1v.y, w1[jt * 16 + c * 4 + 3]);
                }
            }
        }
        float s[8];
#pragma unroll
        for (int o = 0; o < 8; ++o) {
            float2 f = unpk(acc[o]);
            float v = f.x + f.y;
            v += __shfl_xor_sync(0xffffffffu, v, 1);
            v += __shfl_xor_sync(0xffffffffu, v, 2);
            v += __shfl_xor_sync(0xffffffffu, v, 4);
            s[o] = v;
        }
        if (kl == 0) {
            if (g1 == 0) {
#pragma unroll
                for (int b = 0; b < 4; ++b)
#pragma unroll
                    for (int jt = 0; jt < 2; ++jt) {
                        int jloc = jb + jl * 2 + jt;
                        sm[R_Z + b * 68 + jloc] =
                            sigm(s[b * 2 + jt] + xgb[b * 204 + jloc]);
                    }
            } else {
                float rr[8];
#pragma unroll
                for (int b = 0; b < 4; ++b)
#pragma unroll
                    for (int jt = 0; jt < 2; ++jt) {
                        int jloc = jb + jl * 2 + jt;
                        int e = j0 + jloc;
                        float hp = sm[R_H + b * 260 + swq(e >> 2) * 4 + (e & 3)];
                        rr[b * 2 + jt] =
                            sigm(s[b * 2 + jt] + xgb[b * 204 + 68 + jloc]) * hp;
                    }
                float pr[8];
#pragma unroll
                for (int o = 0; o < 8; ++o)
                    pr[o] = __shfl_xor_sync(0x01010101u, rr[o], 8);
                if ((jl & 1) == 0) {
#pragma unroll
                    for (int b = 0; b < 4; ++b) {
                        float4 v = make_float4(rr[b * 2], rr[b * 2 + 1],
                                               pr[b * 2], pr[b * 2 + 1]);
                        uint32_t off = offRH + (uint32_t)b * 1040u;
#pragma unroll
                        for (int p = 0; p < 4; ++p) st_clu_v4(rbase[p] + off, v);
                    }
                }
            }
        }
        if (tid < 192 && t + 1 < S)
            *(float4*)(sm + R_XG + ((t + 1) & 1) * 816 + pb * 204 + pg * 68 + pq * 4) = pxv;
        clu_arrive(); clu_wait();

        const float* Rb = sm + R_RH + b2 * 260;
        ull cacc[4] = {0ull, 0ull, 0ull, 0ull};
#pragma unroll
        for (int i = 0; i < 8; ++i) {
            const int pq2 = ks * 8 + ((i + ks) & 7);
            ulonglong2 rv = *(const ulonglong2*)(Rb + pq2 * 4);
            const float* wp = wp2 + pq2 * 4;
#pragma unroll
            for (int jj = 0; jj < 4; ++jj) {
                ulonglong2 wv = *(const ulonglong2*)(wp + jj * 256);
                ffma2(cacc[jj], rv.x, wv.x);
                ffma2(cacc[jj], rv.y, wv.y);
            }
        }
        float cv[4];
#pragma unroll
        for (int o = 0; o < 4; ++o) {
            float2 f = unpk(cacc[o]);
            float v = f.x + f.y;
            v += __shfl_xor_sync(0xffffffffu, v, 4);
            v += __shfl_xor_sync(0xffffffffu, v, 8);
            v += __shfl_xor_sync(0xffffffffu, v, 16);
            cv[o] = v;
        }
        if (lane < 4) {
            float4 hp = *(const float4*)(sm + R_H + b2 * 260 + swq(qh) * 4);
            float4 zg = *(const float4*)(sm + R_Z + b2 * 68 + jc);
            const float* xc = xgb + b2 * 204 + 136 + jc;
            float4 hn;
            hn.x = fmaf(zg.x, tanh_f(cv[0] + xc[0]) - hp.x, hp.x);
            hn.y = fmaf(zg.y, tanh_f(cv[1] + xc[1]) - hp.y, hp.y);
            hn.z = fmaf(zg.z, tanh_f(cv[2] + xc[2]) - hp.z, hp.z);
            hn.w = fmaf(zg.w, tanh_f(cv[3] + xc[3]) - hp.w, hp.w);
            uint32_t off = offH + (uint32_t)b2 * 1040u;
#pragma unroll
            for (int p = 0; p < 4; ++p) st_clu_v4(rbase[p] + off, hn);
            *(float4*)(outp + (size_t)t * 256) = hn;
        }
        clu_arrive(); clu_wait();
    }
}

extern "C" void kernel_launch(void* const* d_in, const int* in_sizes, int n_in,
                              void* d_out, int out_size) {
    const float* x   = (const float*)d_in[0];
    const float* h0  = (const float*)d_in[1];
    const float* Wzx = (const float*)d_in[2];
    const float* bz  = (const float*)d_in[3];
    const float* Wzh = (const float*)d_in[4];
    const float* Wrx = (const float*)d_in[5];
    const float* br  = (const float*)d_in[6];
    const float* Wrh = (const float*)d_in[7];
    const float* Wcx = (const float*)d_in[8];
    const float* bc  = (const float*)d_in[9];
    const float* Wch = (const float*)d_in[10];
    float* out = (float*)d_out;

    cudaFuncSetAttribute(xproj_kernel, cudaFuncAttributeMaxDynamicSharedMemorySize,
                         (int)PRE_SMEM_BYTES);
    cudaFuncSetAttribute(gru_rec, cudaFuncAttributeMaxDynamicSharedMemorySize,
                         (int)REC_SMEM_BYTES);

    // Phase 1: input projections — x read once per CTA (m-tile resident)
    xproj_kernel<<<1024, 256, PRE_SMEM_BYTES>>>(x, Wzx, bz, Wrx, br, Wcx, bc);
    // Phase 2: recurrence (R7 structure)
    gru_rec<<<128, 512, REC_SMEM_BYTES>>>(h0, Wzh, Wrh, Wch, out);
}